// round 14
// baseline (speedup 1.0000x reference)
#include <cuda_runtime.h>
#include <cuda_bf16.h>
#include <math.h>

#define Hh 512
#define Bb 64
#define Ss 512
#define Ii 128
#define G4 2048
#define NCTA 64

// ---------------- device-global scratch (no allocations allowed) ----------------
__device__ float g_act[Ss * Bb * Hh];   // (S,B,H): quantum out q, then hs per layer
__device__ float g_xp[Ss * G4 * Bb];    // (S, 4H, B) x-projection, transposed for lstm
__device__ float g_cw[Ii * Hh];         // cos(theta+noise), layout (I,H)
__device__ float g_sw[Ii * Hh];         // sin(phi+noise),   layout (I,H)
__device__ float g_fc1[Bb * Hh];
__device__ uint2 g_hsp[2 * 64 * 256];   // double-buffered split-bf16 h: [buf][n][kp]
__device__ unsigned g_flags[NCTA];      // per-CTA progress flags (reset in k_trig)

// ---------------- acquire/release flag ops ----------------
__device__ __forceinline__ void flag_release(unsigned* p, unsigned v) {
    asm volatile("st.release.gpu.global.u32 [%0], %1;" :: "l"(p), "r"(v) : "memory");
}
__device__ __forceinline__ unsigned flag_acquire(const unsigned* p) {
    unsigned v;
    asm volatile("ld.acquire.gpu.global.u32 %0, [%1];" : "=r"(v) : "l"(p) : "memory");
    return v;
}

// ---------------- cp.async 16B ----------------
__device__ __forceinline__ void cpasync16(unsigned dst, const void* src) {
    asm volatile("cp.async.cg.shared.global [%0], [%1], 16;" :: "r"(dst), "l"(src));
}

// ---------------- tf32 helpers (xproj) ----------------
__device__ __forceinline__ unsigned f2tf32(float x) {
    unsigned u;
    asm("cvt.rna.tf32.f32 %0, %1;" : "=r"(u) : "f"(x));
    return u;
}
__device__ __forceinline__ float2 split2(float x) {
    float hi = __uint_as_float(f2tf32(x));
    float lo = __uint_as_float(f2tf32(x - hi));
    return make_float2(hi, lo);
}
__device__ __forceinline__ void mma_tf32(float c[4],
                                         unsigned a0, unsigned a1, unsigned a2, unsigned a3,
                                         unsigned b0, unsigned b1) {
    asm volatile(
        "mma.sync.aligned.m16n8k8.row.col.f32.tf32.tf32.f32 "
        "{%0,%1,%2,%3},{%4,%5,%6,%7},{%8,%9},{%0,%1,%2,%3};\n"
        : "+f"(c[0]), "+f"(c[1]), "+f"(c[2]), "+f"(c[3])
        : "r"(a0), "r"(a1), "r"(a2), "r"(a3), "r"(b0), "r"(b1));
}

// ---------------- bf16 helpers (lstm) ----------------
__device__ __forceinline__ void mma_bf16(float c[4],
                                         unsigned a0, unsigned a1, unsigned a2, unsigned a3,
                                         unsigned b0, unsigned b1) {
    asm volatile(
        "mma.sync.aligned.m16n8k16.row.col.f32.bf16.bf16.f32 "
        "{%0,%1,%2,%3},{%4,%5,%6,%7},{%8,%9},{%0,%1,%2,%3};\n"
        : "+f"(c[0]), "+f"(c[1]), "+f"(c[2]), "+f"(c[3])
        : "r"(a0), "r"(a1), "r"(a2), "r"(a3), "r"(b0), "r"(b1));
}
__device__ __forceinline__ unsigned pack_bf16(float v1_hi, float v0_lo) {
    unsigned w;
    asm("cvt.rn.bf16x2.f32 %0, %1, %2;" : "=r"(w) : "f"(v1_hi), "f"(v0_lo));
    return w;
}
__device__ __forceinline__ float bf16rt(float v) {
    return __bfloat162float(__float2bfloat16(v));
}

// fast activations (__expf: MUFU-based, rel err ~2^-21)
__device__ __forceinline__ float fsig(float x) {
    return __fdividef(1.0f, 1.0f + __expf(-x));
}
__device__ __forceinline__ float ftanh(float x) {
    return 1.0f - __fdividef(2.0f, __expf(2.0f * x) + 1.0f);
}

// ---------------- trig precompute (+ flag reset each launch) ----------------
__global__ void k_trig(const float* __restrict__ th, const float* __restrict__ ph,
                       const float* __restrict__ tn, const float* __restrict__ pn) {
    if (blockIdx.x == 0 && threadIdx.x < NCTA) g_flags[threadIdx.x] = 0u;
    int i = blockIdx.x * 256 + threadIdx.x;
    if (i < Ii * Hh) {
        g_cw[i] = cosf(th[i] + tn[i]);
        g_sw[i] = sinf(ph[i] + pn[i]);
    }
}

// ---------------- quantum layer: q[s][b][h] = sqrt(real^2 + imag^2) -------------
__global__ void __launch_bounds__(256) k_quant(const float* __restrict__ x) {
    __shared__ float As[16][68], Cs[16][68], Sm[16][68];
    int m0 = blockIdx.x * 64, n0 = blockIdx.y * 64;
    int tid = threadIdx.x;
    int tx = tid & 15, ty = tid >> 4;
    float aR[4][4] = {}, aI[4][4] = {};

    for (int kc = 0; kc < Ii; kc += 16) {
        {
            int ml = tid >> 2, k4 = tid & 3;
            float4 v = *(const float4*)(x + (size_t)(m0 + ml) * Ii + kc + k4 * 4);
            As[k4 * 4 + 0][ml] = v.x; As[k4 * 4 + 1][ml] = v.y;
            As[k4 * 4 + 2][ml] = v.z; As[k4 * 4 + 3][ml] = v.w;
        }
        {
            int k = tid >> 4, n4 = tid & 15;
            float4 c = *(const float4*)(g_cw + (size_t)(kc + k) * Hh + n0 + n4 * 4);
            float4 s = *(const float4*)(g_sw + (size_t)(kc + k) * Hh + n0 + n4 * 4);
            *(float4*)&Cs[k][n4 * 4] = c;
            *(float4*)&Sm[k][n4 * 4] = s;
        }
        __syncthreads();
        #pragma unroll
        for (int k = 0; k < 16; k++) {
            float4 a  = *(const float4*)&As[k][ty * 4];
            float4 bc = *(const float4*)&Cs[k][tx * 4];
            float4 bs = *(const float4*)&Sm[k][tx * 4];
            float av[4] = {a.x, a.y, a.z, a.w};
            float cv[4] = {bc.x, bc.y, bc.z, bc.w};
            float sv[4] = {bs.x, bs.y, bs.z, bs.w};
            #pragma unroll
            for (int i = 0; i < 4; i++) {
                #pragma unroll
                for (int j = 0; j < 4; j++) {
                    aR[i][j] += av[i] * cv[j];
                    aI[i][j] += av[i] * sv[j];
                }
            }
        }
        __syncthreads();
    }
    #pragma unroll
    for (int i = 0; i < 4; i++) {
        int m = m0 + ty * 4 + i;
        int b = m >> 9, s = m & 511;
        float4 o;
        o.x = sqrtf(aR[i][0] * aR[i][0] + aI[i][0] * aI[i][0]);
        o.y = sqrtf(aR[i][1] * aR[i][1] + aI[i][1] * aI[i][1]);
        o.z = sqrtf(aR[i][2] * aR[i][2] + aI[i][2] * aI[i][2]);
        o.w = sqrtf(aR[i][3] * aR[i][3] + aI[i][3] * aI[i][3]);
        *(float4*)(g_act + (size_t)s * (Bb * Hh) + (size_t)b * Hh + n0 + tx * 4) = o;
    }
}

// ---------------- x-projection (tensor cores, split tf32 3-mma) -----------------
#define PIT 133
#define XBUF (32 * PIT)
#define XSMEM (2 * XBUF * 8)

__global__ void __launch_bounds__(512, 1) k_xproj(const float* __restrict__ W,
                                                  const float* __restrict__ bi,
                                                  const float* __restrict__ bh,
                                                  float* __restrict__ xpo) {
    extern __shared__ float2 dyn[];
    __shared__ float bsum[128];

    const int tid = threadIdx.x;
    const int m0 = blockIdx.x * 128;
    const int n0 = blockIdx.y * 128;
    const int lane = tid & 31, warp = tid >> 5;
    const int wm0 = (warp & 3) * 32;
    const int wn0 = (warp >> 2) * 32;
    const int g = lane >> 2, t = lane & 3;

    if (tid < 128) bsum[tid] = bi[n0 + tid] + bh[n0 + tid];

    const int srow = tid >> 2;
    const int sks  = (tid & 3) * 4;
    const float* gA = g_act + (size_t)(m0 + srow) * Hh + sks;
    const float* gB = W + (size_t)(n0 + srow) * Hh + sks;

    float4 ra = *(const float4*)(gA);
    float4 rb = *(const float4*)(gB);

    float acc[2][4][4];
    #pragma unroll
    for (int i = 0; i < 2; i++)
        #pragma unroll
        for (int j = 0; j < 4; j++)
            #pragma unroll
            for (int r = 0; r < 4; r++) acc[i][j][r] = 0.0f;

    {
        float av[4] = {ra.x, ra.y, ra.z, ra.w};
        float bv[4] = {rb.x, rb.y, rb.z, rb.w};
        #pragma unroll
        for (int j = 0; j < 4; j++) {
            dyn[(sks + j) * PIT + srow] = split2(av[j]);
            dyn[16 * PIT + (sks + j) * PIT + srow] = split2(bv[j]);
        }
    }
    __syncthreads();

    for (int it = 0; it < 32; ++it) {
        const float2* Ab = dyn + (it & 1) * XBUF;
        const float2* Bbuf = Ab + 16 * PIT;

        if (it < 31) {
            gA += 16; gB += 16;
            ra = *(const float4*)(gA);
            rb = *(const float4*)(gB);
        }

        #pragma unroll
        for (int ko = 0; ko < 16; ko += 8) {
            float2 Af[2][4];
            #pragma unroll
            for (int mt = 0; mt < 2; mt++) {
                int r0 = wm0 + mt * 16 + g;
                Af[mt][0] = Ab[(ko + t) * PIT + r0];
                Af[mt][1] = Ab[(ko + t) * PIT + r0 + 8];
                Af[mt][2] = Ab[(ko + t + 4) * PIT + r0];
                Af[mt][3] = Ab[(ko + t + 4) * PIT + r0 + 8];
            }
            float2 Bf[4][2];
            #pragma unroll
            for (int nt = 0; nt < 4; nt++) {
                int n = wn0 + nt * 8 + g;
                Bf[nt][0] = Bbuf[(ko + t) * PIT + n];
                Bf[nt][1] = Bbuf[(ko + t + 4) * PIT + n];
            }
            #pragma unroll
            for (int mt = 0; mt < 2; mt++) {
                unsigned ah0 = __float_as_uint(Af[mt][0].x), ah1 = __float_as_uint(Af[mt][1].x);
                unsigned ah2 = __float_as_uint(Af[mt][2].x), ah3 = __float_as_uint(Af[mt][3].x);
                unsigned al0 = __float_as_uint(Af[mt][0].y), al1 = __float_as_uint(Af[mt][1].y);
                unsigned al2 = __float_as_uint(Af[mt][2].y), al3 = __float_as_uint(Af[mt][3].y);
                #pragma unroll
                for (int nt = 0; nt < 4; nt++) {
                    unsigned bh0 = __float_as_uint(Bf[nt][0].x);
                    unsigned bh1 = __float_as_uint(Bf[nt][1].x);
                    unsigned bl0 = __float_as_uint(Bf[nt][0].y);
                    unsigned bl1 = __float_as_uint(Bf[nt][1].y);
                    mma_tf32(acc[mt][nt], ah0, ah1, ah2, ah3, bh0, bh1);
                    mma_tf32(acc[mt][nt], ah0, ah1, ah2, ah3, bl0, bl1);
                    mma_tf32(acc[mt][nt], al0, al1, al2, al3, bh0, bh1);
                }
            }
        }

        if (it < 31) {
            float2* An = dyn + ((it + 1) & 1) * XBUF;
            float av[4] = {ra.x, ra.y, ra.z, ra.w};
            float bv[4] = {rb.x, rb.y, rb.z, rb.w};
            #pragma unroll
            for (int j = 0; j < 4; j++) {
                An[(sks + j) * PIT + srow] = split2(av[j]);
                An[16 * PIT + (sks + j) * PIT + srow] = split2(bv[j]);
            }
        }
        __syncthreads();
    }

    #pragma unroll
    for (int mt = 0; mt < 2; mt++) {
        int r0g = m0 + wm0 + mt * 16 + g;
        int s0 = r0g >> 6, b0 = r0g & 63;
        int s1 = (r0g + 8) >> 6, b1 = (r0g + 8) & 63;
        #pragma unroll
        for (int nt = 0; nt < 4; nt++) {
            int col = wn0 + nt * 8 + 2 * t;
            float bs0 = bsum[col], bs1 = bsum[col + 1];
            size_t i00 = (size_t)s0 * 131072 + (size_t)(n0 + col) * 64 + b0;
            size_t i10 = (size_t)s1 * 131072 + (size_t)(n0 + col) * 64 + b1;
            xpo[i00]      = acc[mt][nt][0] + bs0;
            xpo[i00 + 64] = acc[mt][nt][1] + bs1;
            xpo[i10]      = acc[mt][nt][2] + bs0;
            xpo[i10 + 64] = acc[mt][nt][3] + bs1;
        }
    }
}

// ---------------- persistent LSTM recurrence, split-bf16 tensor cores -----------
// 64 CTAs x 512 thr (16 warps: 2m x 8n). CTA owns 8 hidden units -> 32 gate rows.
// Per step: C[32,64] = W[32,512].h[512,64], 3-mma split bf16, fp32 acc.
// Staging pipelined in 2 k-halves (cp.async groups) overlapping the mma halves.
#define LP 258
#define L2_HOFF (32 * LP)
#define L2_F2   (L2_HOFF + 64 * LP)
#define LSTM2_SMEM (L2_F2 * 8 + 32 * 66 * 4)

__global__ void __launch_bounds__(512, 1) k_lstm2(const float* __restrict__ Whh,
                                                  const float* __restrict__ xp,
                                                  float* __restrict__ hs,
                                                  uint2* __restrict__ hsp,
                                                  int base, int store_hs) {
    extern __shared__ float2 sm2[];
    float2* Wsm = sm2;
    float2* Hsm = sm2 + L2_HOFF;
    float*  gt  = (float*)(sm2 + L2_F2);

    const int tid = threadIdx.x;
    const int cta = blockIdx.x;
    const int u0  = cta * 8;
    const int lane = tid & 31, warp = tid >> 5;
    const int mw = warp >> 3, nw = warp & 7;      // 2 m-tiles x 8 n-tiles
    const int gi = lane >> 2, t = lane & 3;
    const unsigned hsm_u32 = (unsigned)__cvta_generic_to_shared(Hsm);

    // ---- load & split Whh slice: 32 m x 256 kp = 8192 float2 ----
    #pragma unroll
    for (int i = 0; i < 16; i++) {
        int idx = tid + 512 * i;
        int m = idx >> 8, kp = idx & 255;
        int row = (m >> 3) * Hh + u0 + (m & 7);
        float2 w = *(const float2*)(Whh + (size_t)row * Hh + 2 * kp);
        float h0 = bf16rt(w.x), h1 = bf16rt(w.y);
        unsigned whi = pack_bf16(w.y, w.x);
        unsigned wlo = pack_bf16(w.y - h1, w.x - h0);
        Wsm[m * LP + kp] = make_float2(__uint_as_float(whi), __uint_as_float(wlo));
    }
    __syncthreads();

    // epilogue mapping (tid < 256): n = batch, up = unit-pair
    const int en = tid & 63;
    const int up = (tid >> 6) & 3;
    float c0 = 0.0f, c1 = 0.0f;

    // mma fragment row bases
    const int mrow = (mw * 16 + gi) * LP;
    const int nrow = (nw * 8 + gi) * LP;

    for (int s = 0; s < Ss; s++) {
        // ---- prefetch xp gates for this step (independent of h) ----
        float xv[8];
        if (tid < 256) {
            const float* xr = xp + (size_t)s * (G4 * Bb) + (size_t)(u0 + 2 * up) * 64 + en;
            #pragma unroll
            for (int g = 0; g < 4; g++) {
                xv[g]     = xr[(size_t)g * 32768];
                xv[4 + g] = xr[(size_t)g * 32768 + 64];
            }
        }

        if (s > 0) {
            // ---- wait for all CTAs to publish h(s-1) ----
            if (tid < NCTA) {
                unsigned target = (unsigned)(base + s);
                while (flag_acquire(&g_flags[tid]) < target) {}
            }
            __syncthreads();

            // ---- stage split h via cp.async, two k-half groups ----
            const uint2* src = hsp + (size_t)((s + 1) & 1) * (64 * 256);
            #pragma unroll
            for (int i = 0; i < 8; i++) {
                int idx = tid + 512 * i;          // 4096: k-half 0 (j<64 -> kp<128)
                int n = idx >> 6, j = idx & 63;
                cpasync16(hsm_u32 + (unsigned)((n * LP + 2 * j) * 8),
                          src + n * 256 + j * 2);
            }
            asm volatile("cp.async.commit_group;" ::: "memory");
            #pragma unroll
            for (int i = 0; i < 8; i++) {
                int idx = tid + 512 * i;          // k-half 1 (j in 64..127)
                int n = idx >> 6, j = (idx & 63) + 64;
                cpasync16(hsm_u32 + (unsigned)((n * LP + 2 * j) * 8),
                          src + n * 256 + j * 2);
            }
            asm volatile("cp.async.commit_group;" ::: "memory");

            float acc[4] = {};

            // ---- half 0: kp < 128 ----
            asm volatile("cp.async.wait_group 1;" ::: "memory");
            __syncthreads();
            #pragma unroll 4
            for (int kt = 0; kt < 16; kt++) {
                int kp0 = kt * 8 + t;
                float2 a0 = Wsm[mrow + kp0];
                float2 a1 = Wsm[mrow + 8 * LP + kp0];
                float2 a2 = Wsm[mrow + kp0 + 4];
                float2 a3 = Wsm[mrow + 8 * LP + kp0 + 4];
                float2 b0 = Hsm[nrow + kp0];
                float2 b1 = Hsm[nrow + kp0 + 4];
                mma_bf16(acc, __float_as_uint(a0.x), __float_as_uint(a1.x),
                              __float_as_uint(a2.x), __float_as_uint(a3.x),
                              __float_as_uint(b0.x), __float_as_uint(b1.x));
                mma_bf16(acc, __float_as_uint(a0.x), __float_as_uint(a1.x),
                              __float_as_uint(a2.x), __float_as_uint(a3.x),
                              __float_as_uint(b0.y), __float_as_uint(b1.y));
                mma_bf16(acc, __float_as_uint(a0.y), __float_as_uint(a1.y),
                              __float_as_uint(a2.y), __float_as_uint(a3.y),
                              __float_as_uint(b0.x), __float_as_uint(b1.x));
            }

            // ---- half 1: kp >= 128 ----
            asm volatile("cp.async.wait_group 0;" ::: "memory");
            __syncthreads();
            #pragma unroll 4
            for (int kt = 16; kt < 32; kt++) {
                int kp0 = kt * 8 + t;
                float2 a0 = Wsm[mrow + kp0];
                float2 a1 = Wsm[mrow + 8 * LP + kp0];
                float2 a2 = Wsm[mrow + kp0 + 4];
                float2 a3 = Wsm[mrow + 8 * LP + kp0 + 4];
                float2 b0 = Hsm[nrow + kp0];
                float2 b1 = Hsm[nrow + kp0 + 4];
                mma_bf16(acc, __float_as_uint(a0.x), __float_as_uint(a1.x),
                              __float_as_uint(a2.x), __float_as_uint(a3.x),
                              __float_as_uint(b0.x), __float_as_uint(b1.x));
                mma_bf16(acc, __float_as_uint(a0.x), __float_as_uint(a1.x),
                              __float_as_uint(a2.x), __float_as_uint(a3.x),
                              __float_as_uint(b0.y), __float_as_uint(b1.y));
                mma_bf16(acc, __float_as_uint(a0.y), __float_as_uint(a1.y),
                              __float_as_uint(a2.y), __float_as_uint(a3.y),
                              __float_as_uint(b0.x), __float_as_uint(b1.x));
            }

            int r0 = mw * 16 + gi;
            int col0 = nw * 8 + 2 * t;
            *(float2*)&gt[r0 * 66 + col0]       = make_float2(acc[0], acc[1]);
            *(float2*)&gt[(r0 + 8) * 66 + col0] = make_float2(acc[2], acc[3]);
            __syncthreads();
        }

        // ---- fused epilogue + pack (tid < 256): units (2up, 2up+1), batch en ----
        if (tid < 256) {
            float g0[4], g1[4];
            #pragma unroll
            for (int g = 0; g < 4; g++) {
                float v0 = xv[g], v1 = xv[4 + g];
                if (s > 0) {
                    v0 += gt[(g * 8 + 2 * up) * 66 + en];
                    v1 += gt[(g * 8 + 2 * up + 1) * 66 + en];
                }
                g0[g] = v0; g1[g] = v1;
            }
            float i0 = fsig(g0[0]), f0 = fsig(g0[1]), gg0 = ftanh(g0[2]), o0 = fsig(g0[3]);
            float i1 = fsig(g1[0]), f1 = fsig(g1[1]), gg1 = ftanh(g1[2]), o1 = fsig(g1[3]);
            c0 = (s == 0) ? (i0 * gg0) : (f0 * c0 + i0 * gg0);
            c1 = (s == 0) ? (i1 * gg1) : (f1 * c1 + i1 * gg1);
            float h0 = o0 * ftanh(c0);
            float h1 = o1 * ftanh(c1);
            if (store_hs || s == Ss - 1) {
                *(float2*)&hs[(size_t)s * 32768 + (size_t)en * Hh + u0 + 2 * up] =
                    make_float2(h0, h1);
            }
            float h0r = bf16rt(h0), h1r = bf16rt(h1);
            unsigned whi = pack_bf16(h1, h0);
            unsigned wlo = pack_bf16(h1 - h1r, h0 - h0r);
            hsp[(size_t)(s & 1) * (64 * 256) + en * 256 + (u0 >> 1) + up] =
                make_uint2(whi, wlo);
        }
        __syncthreads();
        if (tid == 0) flag_release(&g_flags[cta], (unsigned)(base + s + 1));
    }
}

// ---------------- FC head ----------------
__global__ void k_fc1(const float* __restrict__ w, const float* __restrict__ bias) {
    int t = blockIdx.x * 256 + threadIdx.x;
    int j = t >> 6, b = t & 63;
    const float* lr = g_act + (size_t)511 * (Bb * Hh) + (size_t)b * Hh;
    const float* wr = w + (size_t)j * Hh;
    float a = 0.0f;
    for (int k = 0; k < Hh; k += 4) {
        float4 wv = *(const float4*)(wr + k);
        float4 lv = *(const float4*)(lr + k);
        a += wv.x * lv.x + wv.y * lv.y + wv.z * lv.z + wv.w * lv.w;
    }
    a += bias[j];
    g_fc1[b * Hh + j] = fmaxf(a, 0.0f);
}

__global__ void k_fc2(const float* __restrict__ w, const float* __restrict__ bias,
                      float* __restrict__ out) {
    __shared__ float red[128];
    int b = blockIdx.x, tid = threadIdx.x;
    float a = 0.0f;
    for (int j = tid; j < Hh; j += 128) a += g_fc1[b * Hh + j] * w[j];
    red[tid] = a;
    __syncthreads();
    for (int s2 = 64; s2 > 0; s2 >>= 1) {
        if (tid < s2) red[tid] += red[tid + s2];
        __syncthreads();
    }
    if (tid == 0) out[b] = red[0] + bias[0];
}

// ---------------- launch ----------------
extern "C" void kernel_launch(void* const* d_in, const int* in_sizes, int n_in,
                              void* d_out, int out_size) {
    const float* x   = (const float*)d_in[0];
    const float* th  = (const float*)d_in[1];
    const float* ph  = (const float*)d_in[2];
    const float* tn  = (const float*)d_in[3];
    const float* pn  = (const float*)d_in[4];
    const float* Wih = (const float*)d_in[5];
    const float* Whh = (const float*)d_in[6];
    const float* bih = (const float*)d_in[7];
    const float* bhh = (const float*)d_in[8];
    const float* f1w = (const float*)d_in[9];
    const float* f1b = (const float*)d_in[10];
    const float* f2w = (const float*)d_in[11];
    const float* f2b = (const float*)d_in[12];
    float* out = (float*)d_out;

    cudaFuncSetAttribute(k_xproj, cudaFuncAttributeMaxDynamicSharedMemorySize, XSMEM);
    cudaFuncSetAttribute(k_lstm2, cudaFuncAttributeMaxDynamicSharedMemorySize, LSTM2_SMEM);

    float* xp_ptr  = nullptr;
    float* act_ptr = nullptr;
    uint2* hsp_ptr = nullptr;
    cudaGetSymbolAddress((void**)&xp_ptr, g_xp);
    cudaGetSymbolAddress((void**)&act_ptr, g_act);
    cudaGetSymbolAddress((void**)&hsp_ptr, g_hsp);

    k_trig<<<256, 256>>>(th, ph, tn, pn);
    k_quant<<<dim3(512, 8), 256>>>(x);

    for (int l = 0; l < 2; l++) {
        k_xproj<<<dim3(256, 16), 512, XSMEM>>>(Wih + (size_t)l * G4 * Hh,
                                               bih + (size_t)l * G4,
                                               bhh + (size_t)l * G4,
                                               xp_ptr);
        k_lstm2<<<NCTA, 512, LSTM2_SMEM>>>(Whh + (size_t)l * G4 * Hh,
                                           xp_ptr, act_ptr, hsp_ptr,
                                           l * Ss, l == 0 ? 1 : 0);
    }

    k_fc1<<<128, 256>>>(f1w, f1b);
    k_fc2<<<64, 128>>>(f2w, f2b, out);
}

// round 15
// speedup vs baseline: 1.2579x; 1.2579x over previous
#include <cuda_runtime.h>
#include <cuda_bf16.h>
#include <math.h>

#define Hh 512
#define Bb 64
#define Ss 512
#define Ii 128
#define G4 2048
#define NCTA 64

// ---------------- device-global scratch (no allocations allowed) ----------------
__device__ float g_act[Ss * Bb * Hh];     // fp32 hs (only layer2 s=511 written/used)
__device__ float g_xp[Ss * G4 * Bb];      // (S, 4H, B) x-projection, transposed
__device__ float g_cw[Ii * Hh];           // cos(theta+noise), layout (I,H)
__device__ float g_sw[Ii * Hh];           // sin(phi+noise),   layout (I,H)
__device__ float g_fc1[Bb * Hh];
__device__ uint2 g_hsp[2 * 64 * 256];     // double-buffered split-bf16 h exchange
__device__ uint2 g_asp[32768 * 256];      // packed split-bf16 A rows (m=s*64+b, kpair)
__device__ uint2 g_wsp[4096 * 256];       // packed split-bf16 Wih rows (both layers)
__device__ unsigned g_flags[NCTA];        // per-CTA progress flags (reset in k_trig)

// ---------------- acquire/release flag ops ----------------
__device__ __forceinline__ void flag_release(unsigned* p, unsigned v) {
    asm volatile("st.release.gpu.global.u32 [%0], %1;" :: "l"(p), "r"(v) : "memory");
}
__device__ __forceinline__ unsigned flag_acquire(const unsigned* p) {
    unsigned v;
    asm volatile("ld.acquire.gpu.global.u32 %0, [%1];" : "=r"(v) : "l"(p) : "memory");
    return v;
}

// ---------------- cp.async 16B ----------------
__device__ __forceinline__ void cpasync16(unsigned dst, const void* src) {
    asm volatile("cp.async.cg.shared.global [%0], [%1], 16;" :: "r"(dst), "l"(src));
}

// ---------------- bf16 helpers ----------------
__device__ __forceinline__ void mma_bf16(float c[4],
                                         unsigned a0, unsigned a1, unsigned a2, unsigned a3,
                                         unsigned b0, unsigned b1) {
    asm volatile(
        "mma.sync.aligned.m16n8k16.row.col.f32.bf16.bf16.f32 "
        "{%0,%1,%2,%3},{%4,%5,%6,%7},{%8,%9},{%0,%1,%2,%3};\n"
        : "+f"(c[0]), "+f"(c[1]), "+f"(c[2]), "+f"(c[3])
        : "r"(a0), "r"(a1), "r"(a2), "r"(a3), "r"(b0), "r"(b1));
}
__device__ __forceinline__ unsigned pack_bf16(float v1_hi, float v0_lo) {
    unsigned w;
    asm("cvt.rn.bf16x2.f32 %0, %1, %2;" : "=r"(w) : "f"(v1_hi), "f"(v0_lo));
    return w;
}
__device__ __forceinline__ float bf16rt(float v) {
    return __bfloat162float(__float2bfloat16(v));
}
// pack two floats into (hi-plane, lo-plane) bf16x2 words
__device__ __forceinline__ uint2 split_pack(float v0, float v1) {
    float r0 = bf16rt(v0), r1 = bf16rt(v1);
    return make_uint2(pack_bf16(v1, v0), pack_bf16(v1 - r1, v0 - r0));
}

// fast activations (__expf: MUFU-based, rel err ~2^-21)
__device__ __forceinline__ float fsig(float x) {
    return __fdividef(1.0f, 1.0f + __expf(-x));
}
__device__ __forceinline__ float ftanh(float x) {
    return 1.0f - __fdividef(2.0f, __expf(2.0f * x) + 1.0f);
}

// ---------------- trig precompute (+ flag reset each launch) ----------------
__global__ void k_trig(const float* __restrict__ th, const float* __restrict__ ph,
                       const float* __restrict__ tn, const float* __restrict__ pn) {
    if (blockIdx.x == 0 && threadIdx.x < NCTA) g_flags[threadIdx.x] = 0u;
    int i = blockIdx.x * 256 + threadIdx.x;
    if (i < Ii * Hh) {
        g_cw[i] = cosf(th[i] + tn[i]);
        g_sw[i] = sinf(ph[i] + pn[i]);
    }
}

// ---------------- pack Wih (both layers) into split-bf16 ----------------
__global__ void k_wsplit(const float* __restrict__ Wih) {
    int idx = blockIdx.x * 256 + threadIdx.x;   // 4096 rows x 256 kpairs
    int r = idx >> 8, kp = idx & 255;
    float2 w = *(const float2*)(Wih + (size_t)r * Hh + 2 * kp);
    g_wsp[idx] = split_pack(w.x, w.y);
}

// ---------------- quantum layer -> packed split-bf16 A rows ---------------------
__global__ void __launch_bounds__(256) k_quant(const float* __restrict__ x) {
    __shared__ float As[16][68], Cs[16][68], Sm[16][68];
    int m0 = blockIdx.x * 64, n0 = blockIdx.y * 64;
    int tid = threadIdx.x;
    int tx = tid & 15, ty = tid >> 4;
    float aR[4][4] = {}, aI[4][4] = {};

    for (int kc = 0; kc < Ii; kc += 16) {
        {
            int ml = tid >> 2, k4 = tid & 3;
            float4 v = *(const float4*)(x + (size_t)(m0 + ml) * Ii + kc + k4 * 4);
            As[k4 * 4 + 0][ml] = v.x; As[k4 * 4 + 1][ml] = v.y;
            As[k4 * 4 + 2][ml] = v.z; As[k4 * 4 + 3][ml] = v.w;
        }
        {
            int k = tid >> 4, n4 = tid & 15;
            float4 c = *(const float4*)(g_cw + (size_t)(kc + k) * Hh + n0 + n4 * 4);
            float4 s = *(const float4*)(g_sw + (size_t)(kc + k) * Hh + n0 + n4 * 4);
            *(float4*)&Cs[k][n4 * 4] = c;
            *(float4*)&Sm[k][n4 * 4] = s;
        }
        __syncthreads();
        #pragma unroll
        for (int k = 0; k < 16; k++) {
            float4 a  = *(const float4*)&As[k][ty * 4];
            float4 bc = *(const float4*)&Cs[k][tx * 4];
            float4 bs = *(const float4*)&Sm[k][tx * 4];
            float av[4] = {a.x, a.y, a.z, a.w};
            float cv[4] = {bc.x, bc.y, bc.z, bc.w};
            float sv[4] = {bs.x, bs.y, bs.z, bs.w};
            #pragma unroll
            for (int i = 0; i < 4; i++) {
                #pragma unroll
                for (int j = 0; j < 4; j++) {
                    aR[i][j] += av[i] * cv[j];
                    aI[i][j] += av[i] * sv[j];
                }
            }
        }
        __syncthreads();
    }
    #pragma unroll
    for (int i = 0; i < 4; i++) {
        int m = m0 + ty * 4 + i;
        int b = m >> 9, s = m & 511;
        size_t row = (size_t)(s * 64 + b) * 256 + (n0 >> 1) + tx * 2;
        float q0 = sqrtf(aR[i][0] * aR[i][0] + aI[i][0] * aI[i][0]);
        float q1 = sqrtf(aR[i][1] * aR[i][1] + aI[i][1] * aI[i][1]);
        float q2 = sqrtf(aR[i][2] * aR[i][2] + aI[i][2] * aI[i][2]);
        float q3 = sqrtf(aR[i][3] * aR[i][3] + aI[i][3] * aI[i][3]);
        g_asp[row]     = split_pack(q0, q1);
        g_asp[row + 1] = split_pack(q2, q3);
    }
}

// ---------------- x-projection: split-bf16 3-mma, packed cp.async staging -------
// C[m][n] = A[m].W[n], m=s*64+b (32768), n (2048), K=512 (256 kpairs, 16 iters).
// Block 128x128, 512 thr / 16 warps (4m x 4n), warp tile 32x32.
#define XP2 22                        // float2 pitch (176B: 16B-aligned, conflict-free)
#define XTILE (128 * XP2)
#define XBUF2 (2 * XTILE)             // A tile + B tile
#define XSMEM2 (2 * XBUF2 * 8)        // double buffered, bytes = 90112

__global__ void __launch_bounds__(512, 1) k_xproj2(const uint2* __restrict__ Asp,
                                                   const uint2* __restrict__ Wsp,
                                                   const float* __restrict__ bi,
                                                   const float* __restrict__ bh,
                                                   float* __restrict__ xpo) {
    extern __shared__ float2 dyn2[];
    __shared__ float bsum[128];

    const int tid = threadIdx.x;
    const int m0 = blockIdx.x * 128;
    const int n0 = blockIdx.y * 128;
    const int lane = tid & 31, warp = tid >> 5;
    const int wm0 = (warp & 3) * 32;
    const int wn0 = (warp >> 2) * 32;
    const int gi = lane >> 2, t = lane & 3;
    const unsigned smem_u32 = (unsigned)__cvta_generic_to_shared(dyn2);

    if (tid < 128) bsum[tid] = bi[n0 + tid] + bh[n0 + tid];

    // staging mapping: idx -> (row, 16B-unit c); unit c covers kpairs 2c,2c+1
    const int srow = tid >> 1;            // will iterate 2x: rows tid>>1 with q
    // use idx scheme: idx = tid + 512*q, row = idx>>3? (1024 units per tile)
    float acc[2][4][4];
    #pragma unroll
    for (int i = 0; i < 2; i++)
        #pragma unroll
        for (int j = 0; j < 4; j++)
            #pragma unroll
            for (int r = 0; r < 4; r++) acc[i][j][r] = 0.0f;
    (void)srow;

    // ---- stage iteration 'it' into buffer (it&1) ----
    auto stage = [&](int it) {
        unsigned base = smem_u32 + (unsigned)((it & 1) * XBUF2 * 8);
        #pragma unroll
        for (int q = 0; q < 2; q++) {
            int idx = tid + 512 * q;      // 0..1023
            int row = idx >> 3, c = idx & 7;
            cpasync16(base + (unsigned)((row * XP2 + 2 * c) * 8),
                      Asp + (size_t)(m0 + row) * 256 + it * 16 + 2 * c);
            cpasync16(base + (unsigned)((XTILE + row * XP2 + 2 * c) * 8),
                      Wsp + (size_t)(n0 + row) * 256 + it * 16 + 2 * c);
        }
        asm volatile("cp.async.commit_group;" ::: "memory");
    };

    stage(0);

    for (int it = 0; it < 16; ++it) {
        if (it < 15) stage(it + 1);
        if (it < 15) asm volatile("cp.async.wait_group 1;" ::: "memory");
        else         asm volatile("cp.async.wait_group 0;" ::: "memory");
        __syncthreads();

        const float2* A  = dyn2 + (it & 1) * XBUF2;
        const float2* Bt = A + XTILE;

        #pragma unroll
        for (int ch = 0; ch < 2; ch++) {
            int kb = ch * 8;
            float2 a[2][4];
            #pragma unroll
            for (int mt = 0; mt < 2; mt++) {
                int r = (wm0 + mt * 16 + gi) * XP2;
                a[mt][0] = A[r + kb + t];
                a[mt][1] = A[r + 8 * XP2 + kb + t];
                a[mt][2] = A[r + kb + t + 4];
                a[mt][3] = A[r + 8 * XP2 + kb + t + 4];
            }
            float2 b[4][2];
            #pragma unroll
            for (int nt = 0; nt < 4; nt++) {
                int rn = (wn0 + nt * 8 + gi) * XP2;
                b[nt][0] = Bt[rn + kb + t];
                b[nt][1] = Bt[rn + kb + t + 4];
            }
            #pragma unroll
            for (int mt = 0; mt < 2; mt++) {
                unsigned ah0 = __float_as_uint(a[mt][0].x), ah1 = __float_as_uint(a[mt][1].x);
                unsigned ah2 = __float_as_uint(a[mt][2].x), ah3 = __float_as_uint(a[mt][3].x);
                unsigned al0 = __float_as_uint(a[mt][0].y), al1 = __float_as_uint(a[mt][1].y);
                unsigned al2 = __float_as_uint(a[mt][2].y), al3 = __float_as_uint(a[mt][3].y);
                #pragma unroll
                for (int nt = 0; nt < 4; nt++) {
                    unsigned bh0 = __float_as_uint(b[nt][0].x);
                    unsigned bh1 = __float_as_uint(b[nt][1].x);
                    unsigned bl0 = __float_as_uint(b[nt][0].y);
                    unsigned bl1 = __float_as_uint(b[nt][1].y);
                    mma_bf16(acc[mt][nt], ah0, ah1, ah2, ah3, bh0, bh1);
                    mma_bf16(acc[mt][nt], ah0, ah1, ah2, ah3, bl0, bl1);
                    mma_bf16(acc[mt][nt], al0, al1, al2, al3, bh0, bh1);
                }
            }
        }
        __syncthreads();   // everyone done with this buffer before it is re-staged
    }

    // epilogue: c0:(gi,2t) c1:(gi,2t+1) c2:(gi+8,2t) c3:(gi+8,2t+1); transposed store
    #pragma unroll
    for (int mt = 0; mt < 2; mt++) {
        int r0g = m0 + wm0 + mt * 16 + gi;
        int s0 = r0g >> 6, b0 = r0g & 63;
        int s1 = (r0g + 8) >> 6, b1 = (r0g + 8) & 63;
        #pragma unroll
        for (int nt = 0; nt < 4; nt++) {
            int col = wn0 + nt * 8 + 2 * t;
            float bs0 = bsum[col], bs1 = bsum[col + 1];
            size_t i00 = (size_t)s0 * 131072 + (size_t)(n0 + col) * 64 + b0;
            size_t i10 = (size_t)s1 * 131072 + (size_t)(n0 + col) * 64 + b1;
            xpo[i00]      = acc[mt][nt][0] + bs0;
            xpo[i00 + 64] = acc[mt][nt][1] + bs1;
            xpo[i10]      = acc[mt][nt][2] + bs0;
            xpo[i10 + 64] = acc[mt][nt][3] + bs1;
        }
    }
}

// ---------------- persistent LSTM recurrence, split-bf16 tensor cores -----------
// 64 CTAs x 256 thr (R12 structure). 3 independent acc chains per n-tile.
// mode 0 (layer1): write packed h rows to g_asp, no fp32 hs.
// mode 1 (layer2): fp32 hs only at s=511 (for fc1), no g_asp.
#define LP 258
#define L2_HOFF (32 * LP)
#define L2_F2   (L2_HOFF + 64 * LP)
#define LSTM2_SMEM (L2_F2 * 8 + 32 * 66 * 4)

__global__ void __launch_bounds__(256, 1) k_lstm2(const float* __restrict__ Whh,
                                                  const float* __restrict__ xp,
                                                  float* __restrict__ hs,
                                                  uint2* __restrict__ hsp,
                                                  int base, int mode) {
    extern __shared__ float2 sm2[];
    float2* Wsm = sm2;
    float2* Hsm = sm2 + L2_HOFF;
    float*  gt  = (float*)(sm2 + L2_F2);

    const int tid = threadIdx.x;
    const int cta = blockIdx.x;
    const int u0  = cta * 8;
    const int lane = tid & 31, warp = tid >> 5;
    const int mw = warp >> 2, nw = warp & 3;
    const int gi = lane >> 2, t = lane & 3;
    const unsigned hsm_u32 = (unsigned)__cvta_generic_to_shared(Hsm);

    // ---- load & split Whh slice ----
    #pragma unroll
    for (int i = 0; i < 32; i++) {
        int idx = tid + 256 * i;
        int m = idx >> 8, kp = idx & 255;
        int row = (m >> 3) * Hh + u0 + (m & 7);
        float2 w = *(const float2*)(Whh + (size_t)row * Hh + 2 * kp);
        uint2 pk = split_pack(w.x, w.y);
        Wsm[m * LP + kp] = make_float2(__uint_as_float(pk.x), __uint_as_float(pk.y));
    }
    __syncthreads();

    const int en = tid & 63;
    const int up = tid >> 6;
    float c0 = 0.0f, c1 = 0.0f;

    const int mrow = (mw * 16 + gi) * LP;
    const int nrow0 = (nw * 8 + gi) * LP;
    const int nrow1 = (nw * 8 + 32 + gi) * LP;

    for (int s = 0; s < Ss; s++) {
        // prefetch xp gates (independent of h)
        float xv[8];
        {
            const float* xr = xp + (size_t)s * (G4 * Bb) + (size_t)(u0 + 2 * up) * 64 + en;
            #pragma unroll
            for (int g = 0; g < 4; g++) {
                xv[g]     = xr[(size_t)g * 32768];
                xv[4 + g] = xr[(size_t)g * 32768 + 64];
            }
        }

        if (s > 0) {
            if (tid < NCTA) {
                unsigned target = (unsigned)(base + s);
                while (flag_acquire(&g_flags[tid]) < target) {}
            }
            __syncthreads();

            const uint2* src = hsp + (size_t)((s + 1) & 1) * (64 * 256);
            #pragma unroll
            for (int i = 0; i < 32; i++) {
                int u4 = tid + 256 * i;
                int n = u4 >> 7, j = u4 & 127;
                cpasync16(hsm_u32 + (unsigned)((n * LP + 2 * j) * 8),
                          src + n * 256 + j * 2);
            }
            asm volatile("cp.async.commit_group;\n\tcp.async.wait_group 0;" ::: "memory");
            __syncthreads();

            // 3-mma split-bf16, 3 independent chains per n-tile
            float a0h[4] = {}, a0m[4] = {}, a0l[4] = {};
            float a1h[4] = {}, a1m[4] = {}, a1l[4] = {};
            #pragma unroll 8
            for (int kt = 0; kt < 32; kt++) {
                int kp0 = kt * 8 + t;
                float2 w0 = Wsm[mrow + kp0];
                float2 w1 = Wsm[mrow + 8 * LP + kp0];
                float2 w2 = Wsm[mrow + kp0 + 4];
                float2 w3 = Wsm[mrow + 8 * LP + kp0 + 4];
                float2 h00 = Hsm[nrow0 + kp0];
                float2 h01 = Hsm[nrow0 + kp0 + 4];
                float2 h10 = Hsm[nrow1 + kp0];
                float2 h11 = Hsm[nrow1 + kp0 + 4];
                unsigned ah0 = __float_as_uint(w0.x), ah1 = __float_as_uint(w1.x);
                unsigned ah2 = __float_as_uint(w2.x), ah3 = __float_as_uint(w3.x);
                unsigned al0 = __float_as_uint(w0.y), al1 = __float_as_uint(w1.y);
                unsigned al2 = __float_as_uint(w2.y), al3 = __float_as_uint(w3.y);
                {
                    unsigned bh0 = __float_as_uint(h00.x), bh1 = __float_as_uint(h01.x);
                    unsigned bl0 = __float_as_uint(h00.y), bl1 = __float_as_uint(h01.y);
                    mma_bf16(a0h, ah0, ah1, ah2, ah3, bh0, bh1);
                    mma_bf16(a0m, ah0, ah1, ah2, ah3, bl0, bl1);
                    mma_bf16(a0l, al0, al1, al2, al3, bh0, bh1);
                }
                {
                    unsigned bh0 = __float_as_uint(h10.x), bh1 = __float_as_uint(h11.x);
                    unsigned bl0 = __float_as_uint(h10.y), bl1 = __float_as_uint(h11.y);
                    mma_bf16(a1h, ah0, ah1, ah2, ah3, bh0, bh1);
                    mma_bf16(a1m, ah0, ah1, ah2, ah3, bl0, bl1);
                    mma_bf16(a1l, al0, al1, al2, al3, bh0, bh1);
                }
            }
            int r0 = mw * 16 + gi;
            int col0 = nw * 8 + 2 * t;
            *(float2*)&gt[r0 * 66 + col0] =
                make_float2(a0h[0] + a0m[0] + a0l[0], a0h[1] + a0m[1] + a0l[1]);
            *(float2*)&gt[(r0 + 8) * 66 + col0] =
                make_float2(a0h[2] + a0m[2] + a0l[2], a0h[3] + a0m[3] + a0l[3]);
            *(float2*)&gt[r0 * 66 + col0 + 32] =
                make_float2(a1h[0] + a1m[0] + a1l[0], a1h[1] + a1m[1] + a1l[1]);
            *(float2*)&gt[(r0 + 8) * 66 + col0 + 32] =
                make_float2(a1h[2] + a1m[2] + a1l[2], a1h[3] + a1m[3] + a1l[3]);
            __syncthreads();
        }

        // fused epilogue + pack: units (2up, 2up+1), batch en
        {
            float g0[4], g1[4];
            #pragma unroll
            for (int g = 0; g < 4; g++) {
                float v0 = xv[g], v1 = xv[4 + g];
                if (s > 0) {
                    v0 += gt[(g * 8 + 2 * up) * 66 + en];
                    v1 += gt[(g * 8 + 2 * up + 1) * 66 + en];
                }
                g0[g] = v0; g1[g] = v1;
            }
            float i0 = fsig(g0[0]), f0 = fsig(g0[1]), gg0 = ftanh(g0[2]), o0 = fsig(g0[3]);
            float i1 = fsig(g1[0]), f1 = fsig(g1[1]), gg1 = ftanh(g1[2]), o1 = fsig(g1[3]);
            c0 = (s == 0) ? (i0 * gg0) : (f0 * c0 + i0 * gg0);
            c1 = (s == 0) ? (i1 * gg1) : (f1 * c1 + i1 * gg1);
            float h0 = o0 * ftanh(c0);
            float h1 = o1 * ftanh(c1);
            uint2 pk = split_pack(h0, h1);
            hsp[(size_t)(s & 1) * (64 * 256) + en * 256 + (u0 >> 1) + up] = pk;
            if (mode == 0) {
                g_asp[((size_t)s * 64 + en) * 256 + (u0 >> 1) + up] = pk;
            } else if (s == Ss - 1) {
                *(float2*)&hs[(size_t)s * 32768 + (size_t)en * Hh + u0 + 2 * up] =
                    make_float2(h0, h1);
            }
        }
        __syncthreads();
        if (tid == 0) flag_release(&g_flags[cta], (unsigned)(base + s + 1));
    }
}

// ---------------- FC head ----------------
__global__ void k_fc1(const float* __restrict__ w, const float* __restrict__ bias) {
    int t = blockIdx.x * 256 + threadIdx.x;
    int j = t >> 6, b = t & 63;
    const float* lr = g_act + (size_t)511 * (Bb * Hh) + (size_t)b * Hh;
    const float* wr = w + (size_t)j * Hh;
    float a = 0.0f;
    for (int k = 0; k < Hh; k += 4) {
        float4 wv = *(const float4*)(wr + k);
        float4 lv = *(const float4*)(lr + k);
        a += wv.x * lv.x + wv.y * lv.y + wv.z * lv.z + wv.w * lv.w;
    }
    a += bias[j];
    g_fc1[b * Hh + j] = fmaxf(a, 0.0f);
}

__global__ void k_fc2(const float* __restrict__ w, const float* __restrict__ bias,
                      float* __restrict__ out) {
    __shared__ float red[128];
    int b = blockIdx.x, tid = threadIdx.x;
    float a = 0.0f;
    for (int j = tid; j < Hh; j += 128) a += g_fc1[b * Hh + j] * w[j];
    red[tid] = a;
    __syncthreads();
    for (int s2 = 64; s2 > 0; s2 >>= 1) {
        if (tid < s2) red[tid] += red[tid + s2];
        __syncthreads();
    }
    if (tid == 0) out[b] = red[0] + bias[0];
}

// ---------------- launch ----------------
extern "C" void kernel_launch(void* const* d_in, const int* in_sizes, int n_in,
                              void* d_out, int out_size) {
    const float* x   = (const float*)d_in[0];
    const float* th  = (const float*)d_in[1];
    const float* ph  = (const float*)d_in[2];
    const float* tn  = (const float*)d_in[3];
    const float* pn  = (const float*)d_in[4];
    const float* Wih = (const float*)d_in[5];
    const float* Whh = (const float*)d_in[6];
    const float* bih = (const float*)d_in[7];
    const float* bhh = (const float*)d_in[8];
    const float* f1w = (const float*)d_in[9];
    const float* f1b = (const float*)d_in[10];
    const float* f2w = (const float*)d_in[11];
    const float* f2b = (const float*)d_in[12];
    float* out = (float*)d_out;

    cudaFuncSetAttribute(k_xproj2, cudaFuncAttributeMaxDynamicSharedMemorySize, XSMEM2);
    cudaFuncSetAttribute(k_lstm2, cudaFuncAttributeMaxDynamicSharedMemorySize, LSTM2_SMEM);

    float* xp_ptr  = nullptr;
    float* act_ptr = nullptr;
    uint2* hsp_ptr = nullptr;
    uint2* asp_ptr = nullptr;
    uint2* wsp_ptr = nullptr;
    cudaGetSymbolAddress((void**)&xp_ptr, g_xp);
    cudaGetSymbolAddress((void**)&act_ptr, g_act);
    cudaGetSymbolAddress((void**)&hsp_ptr, g_hsp);
    cudaGetSymbolAddress((void**)&asp_ptr, g_asp);
    cudaGetSymbolAddress((void**)&wsp_ptr, g_wsp);

    k_trig<<<256, 256>>>(th, ph, tn, pn);
    k_wsplit<<<4096, 256>>>(Wih);
    k_quant<<<dim3(512, 8), 256>>>(x);

    for (int l = 0; l < 2; l++) {
        k_xproj2<<<dim3(256, 16), 512, XSMEM2>>>(asp_ptr,
                                                 wsp_ptr + (size_t)l * 2048 * 256,
                                                 bih + (size_t)l * G4,
                                                 bhh + (size_t)l * G4,
                                                 xp_ptr);
        k_lstm2<<<NCTA, 256, LSTM2_SMEM>>>(Whh + (size_t)l * G4 * Hh,
                                           xp_ptr, act_ptr, hsp_ptr,
                                           l * Ss, l);
    }

    k_fc1<<<128, 256>>>(f1w, f1b);
    k_fc2<<<64, 128>>>(f2w, f2b, out);
}